// round 11
// baseline (speedup 1.0000x reference)
#include <cuda_runtime.h>
#include <cstdint>

#define BATCH      16384
#define FIELD_DIM  100000
#define THREADS    256
#define WARPS      8
#define RPW        2
#define NBLOCKS    (BATCH / (WARPS * RPW))   // 1024
#define PAD        66

// ---- dynamic smem layout (bytes) ----
#define SM_W1    0                                  // 32*66*4 = 8448
#define SM_W2    8448                               // 16*66*4 = 4224
#define SM_BIAS  12672                              // 64*4    = 256
#define SM_SS    12928                              // 8*2*48*4= 3072
#define SM_MBAR  16000                              // 8 * 8B  = 64
#define SM_BUF   16064                              // 16 bufs * 3712B
#define ROWBUF   3712
#define SMEM_TOTAL (SM_BUF + WARPS * RPW * ROWBUF)  // 75456

__device__ __forceinline__ uint32_t smem_u32(const void* p) {
    uint32_t a;
    asm("{ .reg .u64 t; cvta.to.shared.u64 t, %1; cvt.u32.u64 %0, t; }" : "=r"(a) : "l"(p));
    return a;
}

// plain bulk copy gmem->smem, no tensormap needed (sizes/addrs 16B-aligned)
__device__ __forceinline__ void bulk_ld(uint32_t dst, const void* src,
                                        uint32_t bytes, uint32_t mbar) {
    asm volatile(
        "cp.async.bulk.shared::cluster.global.mbarrier::complete_tx::bytes "
        "[%0], [%1], %2, [%3];"
        :: "r"(dst), "l"(src), "r"(bytes), "r"(mbar) : "memory");
}

__global__ __launch_bounds__(THREADS) void bulk_fused_kernel(
    const int*   __restrict__ x,
    const float* __restrict__ t0,   // [800000, 64]
    const float* __restrict__ t1,   // [800000, 32]
    const float* __restrict__ t2,   // [1000000, 16]
    const float* __restrict__ W1, const float* __restrict__ b1,
    const float* __restrict__ W2, const float* __restrict__ b2,
    float*       __restrict__ out)
{
    extern __shared__ char smem[];
    float* sW1f   = (float*)(smem + SM_W1);
    float* sW2f   = (float*)(smem + SM_W2);
    float* sBiasF = (float*)(smem + SM_BIAS);

    const int tid  = threadIdx.x;
    const int warp = tid >> 5;
    const int lane = tid & 31;
    const unsigned FULL = 0xffffffffu;
    const uint32_t sb   = smem_u32(smem);
    const uint32_t mbar = sb + SM_MBAR + warp * 8;

    // ---- mbarrier init (one per warp) ----
    if (lane == 0)
        asm volatile("mbarrier.init.shared.b64 [%0], %1;" :: "r"(mbar), "r"(1) : "memory");

    // ---- stage W: coalesced LDG, transposed STS (pad-66) ----
    #pragma unroll
    for (int i = tid; i < 64 * 32; i += THREADS) {
        int o = i >> 5, k = i & 31;
        sW1f[k * PAD + o] = W1[i];
    }
    #pragma unroll
    for (int i = tid; i < 64 * 16; i += THREADS) {
        int o = i >> 4, k = i & 15;
        sW2f[k * PAD + o] = W2[i];
    }
    if (tid < 64) sBiasF[tid] = 8.f * b1[tid] + 10.f * b2[tid];

    asm volatile("fence.proxy.async.shared::cta;" ::: "memory");
    __syncthreads();

    const int row0 = (blockIdx.x * WARPS + warp) * RPW;

    int i0 = 0, i1 = 0;
    if (lane < 26) {
        i0 = x[(row0 + 0) * 26 + lane];
        i1 = x[(row0 + 1) * 26 + lane];
    }

    const uint32_t buf0 = sb + SM_BUF + (warp * RPW + 0) * ROWBUF;
    const uint32_t buf1 = buf0 + ROWBUF;

    if (lane == 0)
        asm volatile("mbarrier.arrive.expect_tx.shared.b64 _, [%0], %1;"
                     :: "r"(mbar), "r"(2 * ROWBUF) : "memory");
    __syncwarp();

    // ---- each lane issues bulk copies for its own field, both rows ----
    if (lane < 8) {
        unsigned f = lane;
        bulk_ld(buf0 + f * 256, t0 + ((unsigned)i0 + f * FIELD_DIM) * 64u, 256, mbar);
        bulk_ld(buf1 + f * 256, t0 + ((unsigned)i1 + f * FIELD_DIM) * 64u, 256, mbar);
    } else if (lane < 16) {
        unsigned f = lane - 8;
        bulk_ld(buf0 + 2048 + f * 128, t1 + ((unsigned)i0 + f * FIELD_DIM) * 32u, 128, mbar);
        bulk_ld(buf1 + 2048 + f * 128, t1 + ((unsigned)i1 + f * FIELD_DIM) * 32u, 128, mbar);
    } else if (lane < 26) {
        unsigned f = lane - 16;
        bulk_ld(buf0 + 3072 + f * 64, t2 + ((unsigned)i0 + f * FIELD_DIM) * 16u, 64, mbar);
        bulk_ld(buf1 + 3072 + f * 64, t2 + ((unsigned)i1 + f * FIELD_DIM) * 16u, 64, mbar);
    }

    // ---- wait (parity 0, single use per launch) ----
    asm volatile(
        "{\n\t.reg .pred P;\n\t"
        "WL%=:\n\t"
        "mbarrier.try_wait.parity.acquire.cta.shared::cta.b64 P, [%0], %1, 0x989680;\n\t"
        "@!P bra WL%=;\n\t}"
        :: "r"(mbar), "r"(0) : "memory");

    // ---- readback + reduce ----
    const char* bp0 = smem + SM_BUF + (warp * RPW + 0) * ROWBUF;
    const char* bp1 = bp0 + ROWBUF;
    const float2 bias = *(const float2*)&sBiasF[2 * lane];

    float2 acc0 = bias, acc1 = bias;
    #pragma unroll
    for (int f = 0; f < 8; f++) {
        float2 a = *(const float2*)(bp0 + f * 256 + lane * 8);
        float2 b = *(const float2*)(bp1 + f * 256 + lane * 8);
        acc0.x += a.x; acc0.y += a.y;
        acc1.x += b.x; acc1.y += b.y;
    }
    float s1a = 0.f, s1b = 0.f;
    #pragma unroll
    for (int f = 0; f < 8; f++) {
        s1a += *(const float*)(bp0 + 2048 + f * 128 + lane * 4);
        s1b += *(const float*)(bp1 + 2048 + f * 128 + lane * 4);
    }
    const int half = lane >> 4;
    const int l16  = lane & 15;
    float s2a = 0.f, s2b = 0.f;
    #pragma unroll
    for (int p = 0; p < 5; p++) {
        int f = 2 * p + half;
        s2a += *(const float*)(bp0 + 3072 + f * 64 + l16 * 4);
        s2b += *(const float*)(bp1 + 3072 + f * 64 + l16 * 4);
    }
    s2a += __shfl_xor_sync(FULL, s2a, 16);
    s2b += __shfl_xor_sync(FULL, s2b, 16);

    // ---- stage block-sums for uniform broadcast ----
    float* sS = (float*)(smem + SM_SS) + warp * RPW * 48;
    sS[lane] = s1a;
    sS[48 + lane] = s1b;
    if (lane < 16) {
        sS[32 + lane] = s2a;
        sS[48 + 32 + lane] = s2b;
    }
    __syncwarp();

    // ---- projection: 48 k-steps, W-LDS amortized over 2 rows ----
    #pragma unroll
    for (int k4 = 0; k4 < 12; k4++) {
        float4 sa  = *(const float4*)&sS[k4 * 4];
        float4 sb4 = *(const float4*)&sS[48 + k4 * 4];
        #pragma unroll
        for (int j = 0; j < 4; j++) {
            const int k = k4 * 4 + j;
            float2 w;
            if (k < 32) w = *(const float2*)&sW1f[k * PAD + 2 * lane];
            else        w = *(const float2*)&sW2f[(k - 32) * PAD + 2 * lane];
            float va = (j == 0) ? sa.x  : (j == 1) ? sa.y  : (j == 2) ? sa.z  : sa.w;
            float vb = (j == 0) ? sb4.x : (j == 1) ? sb4.y : (j == 2) ? sb4.z : sb4.w;
            acc0.x += w.x * va; acc0.y += w.y * va;
            acc1.x += w.x * vb; acc1.y += w.y * vb;
        }
    }

    ((float2*)(out + (long long)(row0 + 0) * 64))[lane] = acc0;
    ((float2*)(out + (long long)(row0 + 1) * 64))[lane] = acc1;
}

extern "C" void kernel_launch(void* const* d_in, const int* in_sizes, int n_in,
                              void* d_out, int out_size)
{
    const int*   x  = (const int*)  d_in[0];
    const float* t0 = (const float*)d_in[1];
    const float* t1 = (const float*)d_in[2];
    const float* t2 = (const float*)d_in[3];
    const float* W1 = (const float*)d_in[4];
    const float* b1 = (const float*)d_in[5];
    const float* W2 = (const float*)d_in[6];
    const float* b2 = (const float*)d_in[7];
    float* out = (float*)d_out;

    static bool attr_set = false;
    if (!attr_set) {
        cudaFuncSetAttribute(bulk_fused_kernel,
                             cudaFuncAttributeMaxDynamicSharedMemorySize, SMEM_TOTAL);
        attr_set = true;
    }
    bulk_fused_kernel<<<NBLOCKS, THREADS, SMEM_TOTAL>>>(
        x, t0, t1, t2, W1, b1, W2, b2, out);
}